// round 12
// baseline (speedup 1.0000x reference)
#include <cuda_runtime.h>
#include <cuda_fp16.h>
#include <cstdint>

// SDDMM: out[i] = mask_vals[i] + dot(mat1[rows[i], :], mat2[:, cols[i]])
// Inputs: mask_vals f32[1e6], rows i32[1e6], cols i32[1e6],
//         mat1 f32[8192,128], mat2 f32[128,8192]   Output: f32[1e6]
//
// fp16-staged gathers, HFMA2 depth-2 dot, fp32 finish. 8 nnz per
// warp-iteration for MLP=8 and pipelined reduce chains.

#define NNZ  1000000
#define MDIM 8192
#define NDIM 8192
#define KDIM 128

__device__ __half g_m1h[(size_t)MDIM * KDIM];   // mat1 as fp16 [M, K]
__device__ __half g_m2Th[(size_t)NDIM * KDIM];  // mat2^T as fp16 [N, K]

// ---------------------------------------------------------------------------
// Fused prep (one launch): transpose-convert mat2; linear-convert mat1.
// Identity: 256 blk * 256 thr * 4 = 262144 float4 == MDIM*KDIM/4. Exact.
// ---------------------------------------------------------------------------
#define T2_BLOCKS  1024
#define C1_BLOCKS  256
#define C1_PER_THR 4

__global__ void __launch_bounds__(256)
prep_k(const float* __restrict__ mat1, const float* __restrict__ mat2) {
    if (blockIdx.x < T2_BLOCKS) {
        __shared__ float tile[32][33];
        const int tx = threadIdx.x & 31;
        const int ty = threadIdx.x >> 5;
        const int n0 = (blockIdx.x & 255) * 32;
        const int k0 = (blockIdx.x >> 8) * 32;
        #pragma unroll
        for (int r = ty; r < 32; r += 8)
            tile[r][tx] = mat2[(size_t)(k0 + r) * NDIM + n0 + tx];
        __syncthreads();
        #pragma unroll
        for (int r = ty; r < 32; r += 8)
            g_m2Th[(size_t)(n0 + r) * KDIM + k0 + tx] =
                __float2half_rn(tile[tx][r]);
    } else {
        const int b  = blockIdx.x - T2_BLOCKS;
        const int t0 = (b * 256 + threadIdx.x) * C1_PER_THR;
        float4 v[C1_PER_THR];
        #pragma unroll
        for (int j = 0; j < C1_PER_THR; j++)
            v[j] = reinterpret_cast<const float4*>(mat1)[t0 + j];
        #pragma unroll
        for (int j = 0; j < C1_PER_THR; j++) {
            __half2 h0 = __floats2half2_rn(v[j].x, v[j].y);
            __half2 h1 = __floats2half2_rn(v[j].z, v[j].w);
            uint2 pack;
            pack.x = *reinterpret_cast<unsigned int*>(&h0);
            pack.y = *reinterpret_cast<unsigned int*>(&h1);
            reinterpret_cast<uint2*>(g_m1h)[t0 + j] = pack;
        }
    }
}

// ---------------------------------------------------------------------------
// Dot of 8 half pairs: HMUL2/HFMA2 depth-2 chains, one fp32 conversion.
// ---------------------------------------------------------------------------
__device__ __forceinline__ float dot8h(float4 av, float4 bv) {
    const __half2* ah = reinterpret_cast<const __half2*>(&av);
    const __half2* bh = reinterpret_cast<const __half2*>(&bv);
    __half2 p0 = __hmul2(ah[0], bh[0]);
    p0 = __hfma2(ah[1], bh[1], p0);
    __half2 p1 = __hmul2(ah[2], bh[2]);
    p1 = __hfma2(ah[3], bh[3], p1);
    const float2 f0 = __half22float2(p0);
    const float2 f1 = __half22float2(p1);
    return (f0.x + f0.y) + (f1.x + f1.y);
}

// ---------------------------------------------------------------------------
// Grid-stride SDDMM: 8 lanes per nnz, 8 nnz per warp-iteration.
// Each 8-lane group handles nnz (base+grp) and (base+4+grp).
// All 8 data LDG.128 issue before any consumption (MLP=8); the two
// reduce chains interleave. 16 B of output per warp-iter from lanes 0,8,16,24
// (two scalar stores each 16B apart -> 1-2 sectors).
// ---------------------------------------------------------------------------
__global__ void __launch_bounds__(256)
sddmm_k(const float* __restrict__ mask_vals,
        const int* __restrict__ rows,
        const int* __restrict__ cols,
        float* __restrict__ out) {
    const int lane   = threadIdx.x & 31;
    const int sub    = lane & 7;
    const int grp    = lane >> 3;
    const int gwarp  = (blockIdx.x * blockDim.x + threadIdx.x) >> 5;
    const int nwarps = (gridDim.x * blockDim.x) >> 5;

    for (int base = gwarp * 8; base < NNZ; base += nwarps * 8) {
        const int i0 = base + grp;
        const int i1 = base + 4 + grp;
        const int r0 = rows[i0];
        const int c0 = cols[i0];
        const int r1 = rows[i1];
        const int c1 = cols[i1];

        const float4* __restrict__ a40 =
            reinterpret_cast<const float4*>(g_m1h + (size_t)r0 * KDIM);
        const float4* __restrict__ b40 =
            reinterpret_cast<const float4*>(g_m2Th + (size_t)c0 * KDIM);
        const float4* __restrict__ a41 =
            reinterpret_cast<const float4*>(g_m1h + (size_t)r1 * KDIM);
        const float4* __restrict__ b41 =
            reinterpret_cast<const float4*>(g_m2Th + (size_t)c1 * KDIM);

        // 8 independent LDG.128 in flight
        const float4 aL0 = a40[sub];
        const float4 bL0 = b40[sub];
        const float4 aH0 = a40[sub + 8];
        const float4 bH0 = b40[sub + 8];
        const float4 aL1 = a41[sub];
        const float4 bL1 = b41[sub];
        const float4 aH1 = a41[sub + 8];
        const float4 bH1 = b41[sub + 8];

        float s0 = dot8h(aL0, bL0) + dot8h(aH0, bH0);
        float s1 = dot8h(aL1, bL1) + dot8h(aH1, bH1);

        s0 += __shfl_xor_sync(0xFFFFFFFFu, s0, 4);
        s1 += __shfl_xor_sync(0xFFFFFFFFu, s1, 4);
        s0 += __shfl_xor_sync(0xFFFFFFFFu, s0, 2);
        s1 += __shfl_xor_sync(0xFFFFFFFFu, s1, 2);
        s0 += __shfl_xor_sync(0xFFFFFFFFu, s0, 1);
        s1 += __shfl_xor_sync(0xFFFFFFFFu, s1, 1);

        if (sub == 0) {
            out[i0] = mask_vals[i0] + s0;
            out[i1] = mask_vals[i1] + s1;
        }
    }
}

extern "C" void kernel_launch(void* const* d_in, const int* in_sizes, int n_in,
                              void* d_out, int out_size) {
    const float* mask_vals = (const float*)d_in[0];
    const int*   rows      = (const int*)d_in[1];
    const int*   cols      = (const int*)d_in[2];
    const float* mat1      = (const float*)d_in[3];
    const float* mat2      = (const float*)d_in[4];
    float*       out       = (float*)d_out;

    prep_k<<<T2_BLOCKS + C1_BLOCKS, 256>>>(mat1, mat2);
    sddmm_k<<<148 * 8, 256>>>(mask_vals, rows, cols, out);
}

// round 13
// speedup vs baseline: 1.2241x; 1.2241x over previous
#include <cuda_runtime.h>
#include <cuda_fp16.h>
#include <cstdint>

// SDDMM: out[i] = mask_vals[i] + dot(mat1[rows[i], :], mat2[:, cols[i]])
// Inputs: mask_vals f32[1e6], rows i32[1e6], cols i32[1e6],
//         mat1 f32[8192,128], mat2 f32[128,8192]   Output: f32[1e6]
//
// fp16-staged gathers, HFMA2 depth-2 dot, fp32 finish. 4 nnz/warp-iter
// (regs=32 sweet spot), fused int2 indices + software-pipelined prefetch.

#define NNZ  1000000
#define MDIM 8192
#define NDIM 8192
#define KDIM 128

__device__ __half g_m1h[(size_t)MDIM * KDIM];   // mat1 as fp16 [M, K]
__device__ __half g_m2Th[(size_t)NDIM * KDIM];  // mat2^T as fp16 [N, K]
__device__ int2   g_rc[NNZ];                    // fused {row, col}

// ---------------------------------------------------------------------------
// Fused prep (one launch):
//   blocks [0, 1024):       transpose-convert mat2 -> g_m2Th [N,K] fp16
//   blocks [1024, 1280):    convert mat1 -> fp16 (256*256*4 = 262144 float4
//                           == MDIM*KDIM/4. Exact.)
//   blocks [1280, 2257):    fuse rows/cols -> g_rc (4 nnz/thread, guarded:
//                           977*256*4 = 1000448 >= NNZ)
// ---------------------------------------------------------------------------
#define T2_BLOCKS  1024
#define C1_BLOCKS  256
#define RC_BLOCKS  977

__global__ void __launch_bounds__(256)
prep_k(const float* __restrict__ mat1, const float* __restrict__ mat2,
       const int* __restrict__ rows, const int* __restrict__ cols) {
    if (blockIdx.x < T2_BLOCKS) {
        // ---- transpose-convert mat2 ----
        __shared__ float tile[32][33];
        const int tx = threadIdx.x & 31;
        const int ty = threadIdx.x >> 5;
        const int n0 = (blockIdx.x & 255) * 32;
        const int k0 = (blockIdx.x >> 8) * 32;
        #pragma unroll
        for (int r = ty; r < 32; r += 8)
            tile[r][tx] = mat2[(size_t)(k0 + r) * NDIM + n0 + tx];
        __syncthreads();
        #pragma unroll
        for (int r = ty; r < 32; r += 8)
            g_m2Th[(size_t)(n0 + r) * KDIM + k0 + tx] =
                __float2half_rn(tile[tx][r]);
    } else if (blockIdx.x < T2_BLOCKS + C1_BLOCKS) {
        // ---- linear convert mat1 ----
        const int b  = blockIdx.x - T2_BLOCKS;
        const int t0 = (b * 256 + threadIdx.x) * 4;
        float4 v[4];
        #pragma unroll
        for (int j = 0; j < 4; j++)
            v[j] = reinterpret_cast<const float4*>(mat1)[t0 + j];
        #pragma unroll
        for (int j = 0; j < 4; j++) {
            __half2 h0 = __floats2half2_rn(v[j].x, v[j].y);
            __half2 h1 = __floats2half2_rn(v[j].z, v[j].w);
            uint2 pack;
            pack.x = *reinterpret_cast<unsigned int*>(&h0);
            pack.y = *reinterpret_cast<unsigned int*>(&h1);
            reinterpret_cast<uint2*>(g_m1h)[t0 + j] = pack;
        }
    } else {
        // ---- fuse rows/cols into int2 ----
        const int b    = blockIdx.x - T2_BLOCKS - C1_BLOCKS;
        const int base = (b * 256 + threadIdx.x) * 4;
        if (base < NNZ) {
            const int4 r = *reinterpret_cast<const int4*>(rows + base);
            const int4 c = *reinterpret_cast<const int4*>(cols + base);
            int4 lo, hi;
            lo.x = r.x; lo.y = c.x; lo.z = r.y; lo.w = c.y;
            hi.x = r.z; hi.y = c.z; hi.z = r.w; hi.w = c.w;
            reinterpret_cast<int4*>(g_rc + base)[0] = lo;
            reinterpret_cast<int4*>(g_rc + base)[1] = hi;
        }
    }
}

// ---------------------------------------------------------------------------
// Dot of 8 half pairs: HMUL2/HFMA2 depth-2 chains, one fp32 conversion.
// ---------------------------------------------------------------------------
__device__ __forceinline__ float dot8h(float4 av, float4 bv) {
    const __half2* ah = reinterpret_cast<const __half2*>(&av);
    const __half2* bh = reinterpret_cast<const __half2*>(&bv);
    __half2 p0 = __hmul2(ah[0], bh[0]);
    p0 = __hfma2(ah[1], bh[1], p0);
    __half2 p1 = __hmul2(ah[2], bh[2]);
    p1 = __hfma2(ah[3], bh[3], p1);
    const float2 f0 = __half22float2(p0);
    const float2 f1 = __half22float2(p1);
    return (f0.x + f0.y) + (f1.x + f1.y);
}

// ---------------------------------------------------------------------------
// Grid-stride SDDMM: 8 lanes per nnz, 4 nnz per warp-iteration.
// Indices software-pipelined: next iteration's int2 fetched while this
// iteration's data loads are in flight. Mask loaded before the reduce.
// ---------------------------------------------------------------------------
__global__ void __launch_bounds__(256)
sddmm_k(const float* __restrict__ mask_vals, float* __restrict__ out) {
    const int lane   = threadIdx.x & 31;
    const int sub    = lane & 7;
    const int grp    = lane >> 3;
    const int gwarp  = (blockIdx.x * blockDim.x + threadIdx.x) >> 5;
    const int nwarps = (gridDim.x * blockDim.x) >> 5;
    const int stride = nwarps * 4;

    int base = gwarp * 4;
    if (base >= NNZ) return;

    int2 rc = g_rc[base + grp];                // first indices

    while (base < NNZ) {
        const int i = base + grp;

        const float4* __restrict__ a4 =
            reinterpret_cast<const float4*>(g_m1h + (size_t)rc.x * KDIM);
        const float4* __restrict__ b4 =
            reinterpret_cast<const float4*>(g_m2Th + (size_t)rc.y * KDIM);

        // 4 independent data LDG.128
        const float4 aL = a4[sub];
        const float4 bL = b4[sub];
        const float4 aH = a4[sub + 8];
        const float4 bH = b4[sub + 8];

        // Prefetch next iteration's indices while data is in flight
        const int nbase = base + stride;
        int2 rc_next = rc;
        if (nbase < NNZ) rc_next = g_rc[nbase + grp];

        // Mask load early so its latency hides under the reduce
        float mv = 0.0f;
        if (sub == 0) mv = mask_vals[i];

        float s = dot8h(aL, bL) + dot8h(aH, bH);

        s += __shfl_xor_sync(0xFFFFFFFFu, s, 4);
        s += __shfl_xor_sync(0xFFFFFFFFu, s, 2);
        s += __shfl_xor_sync(0xFFFFFFFFu, s, 1);

        if (sub == 0)
            out[i] = mv + s;

        base = nbase;
        rc   = rc_next;
    }
}

extern "C" void kernel_launch(void* const* d_in, const int* in_sizes, int n_in,
                              void* d_out, int out_size) {
    const float* mask_vals = (const float*)d_in[0];
    const int*   rows      = (const int*)d_in[1];
    const int*   cols      = (const int*)d_in[2];
    const float* mat1      = (const float*)d_in[3];
    const float* mat2      = (const float*)d_in[4];
    float*       out       = (float*)d_out;

    prep_k<<<T2_BLOCKS + C1_BLOCKS + RC_BLOCKS, 256>>>(mat1, mat2, rows, cols);
    sddmm_k<<<148 * 8, 256>>>(mask_vals, out);
}